// round 16
// baseline (speedup 1.0000x reference)
#include <cuda_runtime.h>
#include <cuda_fp16.h>
#include <mma.h>
#include <cstdint>

using namespace nvcuda;

// ---------------- problem dims ----------------
#define DIM     256
#define NTREES  512
#define TDEPTH  6
#define UNITS   16
#define LEAVES  64
#define BATCH   1024
#define NJ      (NTREES * TDEPTH)       // 3072 columns (j = n*6+d)

// ---------------- device scratch ----------------
__device__ __align__(16) __half g_xhi[BATCH * DIM];
__device__ __align__(16) __half g_xlo[BATCH * DIM];
__device__ __align__(16) __half g_shi[DIM * NJ];
__device__ __align__(16) __half g_slo[DIM * NJ];
__device__ __align__(16) __half g_rhi[NTREES * UNITS * LEAVES];
__device__ __align__(16) __half g_rlo[NTREES * UNITS * LEAVES];
__device__ __align__(16) float  g_fvT[(size_t)NJ * BATCH];       // 12.5 MB, [j][b]
__device__ __align__(16) float  g_partial[64 * BATCH * UNITS];   // 4 MB
__device__ __align__(16) float  g_red[8 * BATCH * UNITS];        // 512 KB

__device__ __forceinline__ uint32_t h2u(__half2 h) {
    return *reinterpret_cast<uint32_t*>(&h);
}
__device__ __forceinline__ uint32_t smem_u32(const void* p) {
    uint32_t a;
    asm("{ .reg .u64 t; cvta.to.shared.u64 t, %1; cvt.u32.u64 %0, t; }" : "=r"(a) : "l"(p));
    return a;
}
__device__ __forceinline__ void cp_async16(uint32_t dst, const void* src) {
    asm volatile("cp.async.cg.shared.global [%0], [%1], 16;" :: "r"(dst), "l"(src));
}
#define CP_COMMIT()  asm volatile("cp.async.commit_group;" ::: "memory")
#define CP_WAIT(n)   asm volatile("cp.async.wait_group %0;" :: "n"(n) : "memory")

// Raw tensor-core MMA (baseline sm_80 PTX; D += A@B, fp16 in, fp32 accum).
__device__ __forceinline__ void mma16816(float d[4], const uint32_t a[4],
                                         uint32_t b0, uint32_t b1) {
    asm volatile(
        "mma.sync.aligned.m16n8k16.row.col.f32.f16.f16.f32 "
        "{%0,%1,%2,%3}, {%4,%5,%6,%7}, {%8,%9}, {%0,%1,%2,%3};"
        : "+f"(d[0]), "+f"(d[1]), "+f"(d[2]), "+f"(d[3])
        : "r"(a[0]), "r"(a[1]), "r"(a[2]), "r"(a[3]), "r"(b0), "r"(b1));
}

__device__ __forceinline__ void split4(const float* __restrict__ src,
                                       __half* dh, __half* dl, int i4) {
    float4 v = *(const float4*)(src + (size_t)i4 * 4);
    __half2 h01 = __floats2half2_rn(v.x, v.y);
    __half2 h23 = __floats2half2_rn(v.z, v.w);
    __half2 l01 = __floats2half2_rn(v.x - __low2float(h01), v.y - __high2float(h01));
    __half2 l23 = __floats2half2_rn(v.z - __low2float(h23), v.w - __high2float(h23));
    *(uint2*)(dh + (size_t)i4 * 4) = make_uint2(h2u(h01), h2u(h23));
    *(uint2*)(dl + (size_t)i4 * 4) = make_uint2(h2u(l01), h2u(l23));
}

// ---------------------------------------------------------------------------
// Kernel 0: FUSED prep — sparsemax (blocks [0,256)), x split ([256,512)),
// response split ([512,1024)). All three independent; run concurrently.
// ---------------------------------------------------------------------------
__global__ void prep_kernel(const float* __restrict__ fsl,
                            const float* __restrict__ x,
                            const float* __restrict__ resp) {
    const int blk = blockIdx.x;
    const int tid = threadIdx.x;
    if (blk < 256) {
        // sparsemax: 2 rows/thread, float4 in, vector out
        int pr = blk * 256 + tid;                       // row pair 0..65535
        const float4* zp4 = (const float4*)(fsl + (size_t)pr * 12);
        float4 q0 = zp4[0], q1 = zp4[1], q2 = zp4[2];
        float vv[12] = { q0.x, q0.y, q0.z, q0.w, q1.x, q1.y,
                         q1.z, q1.w, q2.x, q2.y, q2.z, q2.w };
        __half oh[12], ol[12];
#pragma unroll
        for (int rr = 0; rr < 2; rr++) {
            float* v = vv + rr * 6;
            float s[TDEPTH];
#pragma unroll
            for (int j = 0; j < TDEPTH; j++) s[j] = v[j];
#pragma unroll
            for (int a = 0; a < TDEPTH - 1; a++)
#pragma unroll
                for (int b = 0; b < TDEPTH - 1 - a; b++)
                    if (s[b] < s[b + 1]) { float t = s[b]; s[b] = s[b + 1]; s[b + 1] = t; }
            float cs[TDEPTH], acc = 0.f; int cnt = 0;
#pragma unroll
            for (int j = 0; j < TDEPTH; j++) {
                acc += s[j]; cs[j] = acc;
                if (s[j] * (float)(j + 1) > acc - 1.f) cnt++;
            }
            float csk = cs[0];
#pragma unroll
            for (int j = 1; j < TDEPTH; j++) if (cnt == j + 1) csk = cs[j];
            float tau = (csk - 1.f) / (float)cnt;
#pragma unroll
            for (int j = 0; j < TDEPTH; j++) {
                float sv = fmaxf(v[j] - tau, 0.f);
                __half hi = __float2half_rn(sv);
                oh[rr * 6 + j] = hi;
                ol[rr * 6 + j] = __float2half_rn(sv - __half2float(hi));
            }
        }
        size_t base = (size_t)pr * 12;
        uint2* dh = (uint2*)(g_shi + base);
        uint2* dl = (uint2*)(g_slo + base);
        const uint2* sh = (const uint2*)oh;
        const uint2* sl = (const uint2*)ol;
#pragma unroll
        for (int q = 0; q < 3; q++) { dh[q] = sh[q]; dl[q] = sl[q]; }
    } else if (blk < 512) {
        split4(x, g_xhi, g_xlo, (blk - 256) * 256 + tid);
    } else {
        split4(resp, g_rhi, g_rlo, (blk - 512) * 256 + tid);
    }
}

// ---------------------------------------------------------------------------
// Kernel 1: fv GEMM via wmma, fp16 3-term split per k-chunk. GM=64 x GN=64,
// stage {x_hi,x_lo,s_hi,s_lo} double-buffered (73.7 KB) -> 3 CTAs/SM.
// (unchanged from R15 — measured corner)
// ---------------------------------------------------------------------------
#define GM 64
#define GN 64
#define GK 64
#define A_LDM 72
#define B_LDM 72
#define A_BUF (GM * A_LDM)               // 4608 halves
#define B_BUF (GK * B_LDM)               // 4608 halves
#define STG_B (2 * A_BUF + 2 * B_BUF)    // 18432 halves = 36864 B
#define S_TOT (STG_B * 2 * 2)            // 73728 B

__global__ __launch_bounds__(256, 3)
void fv_mma_kernel() {
    extern __shared__ __half smh[];
    const uint32_t sbase = smem_u32(smh);

    const int tid = threadIdx.x;
    const int w   = tid >> 5;
    const int wm  = w & 1;
    const int wn  = w >> 1;
    const int j0  = blockIdx.x * GN;
    const int b0  = blockIdx.y * GM;

    auto stage = [&](int k) {
        const int k0  = k * GK;
        const uint32_t base = sbase + (uint32_t)((k & 1) * STG_B) * 2;
        const uint32_t axh = base;
        const uint32_t axl = base + (uint32_t)A_BUF * 2;
        const uint32_t bsh = base + (uint32_t)(2 * A_BUF) * 2;
        const uint32_t bsl = bsh + (uint32_t)B_BUF * 2;
#pragma unroll
        for (int q = 0; q < 2; q++) {
            int id  = tid + q * 256;
            int row = id >> 3, c16 = id & 7;
            const size_t goff = (size_t)(b0 + row) * DIM + k0 + c16 * 8;
            const uint32_t soff = (uint32_t)row * (A_LDM * 2) + c16 * 16;
            cp_async16(axh + soff, g_xhi + goff);
            cp_async16(axl + soff, g_xlo + goff);
        }
#pragma unroll
        for (int q = 0; q < 2; q++) {
            int id  = tid + q * 256;
            int row = id >> 3, c16 = id & 7;
            const size_t goff = (size_t)(k0 + row) * NJ + j0 + c16 * 8;
            const uint32_t soff = (uint32_t)row * (B_LDM * 2) + c16 * 16;
            cp_async16(bsh + soff, g_shi + goff);
            cp_async16(bsl + soff, g_slo + goff);
        }
        CP_COMMIT();
    };

    wmma::fragment<wmma::accumulator, 16, 16, 16, float> c[2];
#pragma unroll
    for (int i = 0; i < 2; i++) wmma::fill_fragment(c[i], 0.f);

    stage(0); stage(1);

#pragma unroll 1
    for (int k = 0; k < 4; k++) {
        if (k < 3) { CP_WAIT(1); } else { CP_WAIT(0); }
        __syncthreads();

        const __half* Axh = smh + (k & 1) * STG_B;
        const __half* Axl = Axh + A_BUF;
        const __half* Bsh = Axh + 2 * A_BUF;
        const __half* Bsl = Bsh + B_BUF;

#pragma unroll
        for (int kk = 0; kk < GK / 16; kk++) {
            wmma::fragment<wmma::matrix_a, 16, 16, 16, __half, wmma::row_major> ah[2], al[2];
            wmma::fragment<wmma::matrix_b, 16, 16, 16, __half, wmma::row_major> bh, bl;
#pragma unroll
            for (int i = 0; i < 2; i++) {
                wmma::load_matrix_sync(ah[i], Axh + (wm * 32 + i * 16) * A_LDM + kk * 16, A_LDM);
                wmma::load_matrix_sync(al[i], Axl + (wm * 32 + i * 16) * A_LDM + kk * 16, A_LDM);
            }
            wmma::load_matrix_sync(bh, Bsh + (kk * 16) * B_LDM + wn * 16, B_LDM);
            wmma::load_matrix_sync(bl, Bsl + (kk * 16) * B_LDM + wn * 16, B_LDM);
#pragma unroll
            for (int i = 0; i < 2; i++) {
                wmma::mma_sync(c[i], ah[i], bh, c[i]);
                wmma::mma_sync(c[i], al[i], bh, c[i]);
                wmma::mma_sync(c[i], ah[i], bl, c[i]);
            }
        }

        __syncthreads();
        if (k + 2 < 4) stage(k + 2);
    }

#pragma unroll
    for (int i = 0; i < 2; i++)
        wmma::store_matrix_sync(
            g_fvT + (size_t)(j0 + wn * 16) * BATCH + b0 + wm * 32 + i * 16,
            c[i], BATCH, wmma::mem_col_major);
}

// ---------------------------------------------------------------------------
// Kernel 2: response contraction — raw mma.sync, W built in registers.
// NT=8 trees/block -> grid 512 (single 86% wave), partials halve to 64 blocks.
// ---------------------------------------------------------------------------
#define BT    128
#define NT    8
#define NBLK  (NTREES / NT)             // 64
#define R_LDM 72

__global__ __launch_bounds__(256, 4)
void resp_mma_kernel(const float* __restrict__ th,
                     const float* __restrict__ lt) {
    __shared__ __half rhi_s[NT * UNITS * R_LDM];       // 18432 B
    __shared__ __half rlo_s[NT * UNITS * R_LDM];
    __shared__ float  th_s[NT * TDEPTH], ei_s[NT * TDEPTH];

    const int tid = threadIdx.x;
    const int w   = tid >> 5;
    const int l   = tid & 31;
    const int n0  = blockIdx.x * NT;
    const int b0  = blockIdx.y * BT;

    {
        const uint2* srch = (const uint2*)(g_rhi + (size_t)(n0 * UNITS) * LEAVES);
        const uint2* srcl = (const uint2*)(g_rlo + (size_t)(n0 * UNITS) * LEAVES);
        for (int i = tid; i < NT * UNITS * LEAVES / 4; i += 256) {
            int row = i >> 4, col = (i & 15) * 4;
            *(uint2*)(rhi_s + row * R_LDM + col) = srch[i];
            *(uint2*)(rlo_s + row * R_LDM + col) = srcl[i];
        }
    }
    if (tid < NT * TDEPTH) {
        th_s[tid] = th[n0 * TDEPTH + tid];
        ei_s[tid] = __expf(-lt[n0 * TDEPTH + tid]);
    }
    __syncthreads();

    const int a  = l & 3;               // leaf-column group
    const int g  = l >> 2;              // row within half-tile / unit index
    const int bg1 = b0 + w * 16 + g;
    const int bg2 = bg1 + 8;

    float fv1[TDEPTH], fv2[TDEPTH];
#pragma unroll
    for (int d = 0; d < TDEPTH; d++) {
        fv1[d] = g_fvT[(size_t)(n0 * TDEPTH + d) * BATCH + bg1];
        fv2[d] = g_fvT[(size_t)(n0 * TDEPTH + d) * BATCH + bg2];
    }

    float D0[4] = {0.f, 0.f, 0.f, 0.f};
    float D1[4] = {0.f, 0.f, 0.f, 0.f};

#pragma unroll 1
    for (int t = 0; t < NT; t++) {
        float wA[2], wB[2];
        float t4[2][2][2];
        float g5p[2], g5n[2];
#pragma unroll
        for (int r = 0; r < 2; r++) {
            const float* fv = r ? fv2 : fv1;
            float gp[TDEPTH], gn[TDEPTH];
#pragma unroll
            for (int d = 0; d < TDEPTH; d++) {
                float tt = (fv[d] - th_s[t * TDEPTH + d]) * ei_s[t * TDEPTH + d];
                gp[d] = __saturatef(fmaf(0.5f, tt, 0.5f));
                gn[d] = 1.f - gp[d];
            }
            float g1s = (a & 1) ? gn[1] : gp[1];
            wA[r] = gp[0] * g1s;
            wB[r] = gn[0] * g1s;
            float g2s = (a >> 1) ? gn[2] : gp[2];
            float t3p = g2s * gp[3], t3n = g2s * gn[3];
            t4[r][0][0] = t3p * gp[4]; t4[r][0][1] = t3n * gp[4];
            t4[r][1][0] = t3p * gn[4]; t4[r][1][1] = t3n * gn[4];
            g5p[r] = gp[5]; g5n[r] = gn[5];
        }

        if (t < NT - 1) {
#pragma unroll
            for (int d = 0; d < TDEPTH; d++) {
                fv1[d] = g_fvT[(size_t)((n0 + t + 1) * TDEPTH + d) * BATCH + bg1];
                fv2[d] = g_fvT[(size_t)((n0 + t + 1) * TDEPTH + d) * BATCH + bg2];
            }
        }

        const __half* rh = rhi_s + t * UNITS * R_LDM;
        const __half* rl = rlo_s + t * UNITS * R_LDM;

#pragma unroll
        for (int kk = 0; kk < 4; kk++) {
            uint32_t Ahi[4], Alo[4];
#pragma unroll
            for (int r = 0; r < 2; r++) {
                float g5s  = (kk >> 1) ? g5n[r] : g5p[r];
                float whiL = t4[r][kk & 1][0] * g5s;
                float whiH = t4[r][kk & 1][1] * g5s;
                float w0 = wA[r] * whiL, w1 = wB[r] * whiL;
                float w2 = wA[r] * whiH, w3 = wB[r] * whiH;
                __half2 hL = __floats2half2_rn(w0, w1);
                __half2 hH = __floats2half2_rn(w2, w3);
                float2 fL = __half22float2(hL);
                float2 fH = __half22float2(hH);
                __half2 lL = __floats2half2_rn(w0 - fL.x, w1 - fL.y);
                __half2 lH = __floats2half2_rn(w2 - fH.x, w3 - fH.y);
                Ahi[r]     = h2u(hL);  Ahi[2 + r] = h2u(hH);
                Alo[r]     = h2u(lL);  Alo[2 + r] = h2u(lH);
            }
            const int off = kk * 16 + a * 2;
            uint32_t bh0 = *(const uint32_t*)(rh + g * R_LDM + off);
            uint32_t bh1 = *(const uint32_t*)(rh + g * R_LDM + off + 8);
            uint32_t bh2 = *(const uint32_t*)(rh + (8 + g) * R_LDM + off);
            uint32_t bh3 = *(const uint32_t*)(rh + (8 + g) * R_LDM + off + 8);
            uint32_t bl0 = *(const uint32_t*)(rl + g * R_LDM + off);
            uint32_t bl1 = *(const uint32_t*)(rl + g * R_LDM + off + 8);
            uint32_t bl2 = *(const uint32_t*)(rl + (8 + g) * R_LDM + off);
            uint32_t bl3 = *(const uint32_t*)(rl + (8 + g) * R_LDM + off + 8);

            mma16816(D0, Ahi, bh0, bh1);
            mma16816(D1, Ahi, bh2, bh3);
            mma16816(D0, Alo, bh0, bh1);
            mma16816(D1, Alo, bh2, bh3);
            mma16816(D0, Ahi, bl0, bl1);
            mma16816(D1, Ahi, bl2, bl3);
        }
    }

    float* p1 = g_partial + ((size_t)blockIdx.x * BATCH + bg1) * UNITS;
    float* p2 = g_partial + ((size_t)blockIdx.x * BATCH + bg2) * UNITS;
    *(float2*)(p1 + a * 2)     = make_float2(D0[0], D0[1]);
    *(float2*)(p2 + a * 2)     = make_float2(D0[2], D0[3]);
    *(float2*)(p1 + 8 + a * 2) = make_float2(D1[0], D1[1]);
    *(float2*)(p2 + 8 + a * 2) = make_float2(D1[2], D1[3]);
}

// ---------------------------------------------------------------------------
// Kernel 3: reduction stage 1 — group p sums partial blocks [8p, 8p+8),
// float4, 8 independent LD.128 per thread.
// ---------------------------------------------------------------------------
__global__ void reduce1_kernel() {
    int tid = blockIdx.x * blockDim.x + threadIdx.x;   // 0..32767
    int p  = tid >> 12;                                // 0..7
    int i4 = tid & 4095;
    const float4* src = (const float4*)g_partial + (size_t)(p * 8) * 4096 + i4;
    float4 acc = make_float4(0.f, 0.f, 0.f, 0.f);
#pragma unroll
    for (int k = 0; k < 8; k++) {
        float4 v = src[(size_t)k * 4096];
        acc.x += v.x; acc.y += v.y; acc.z += v.z; acc.w += v.w;
    }
    ((float4*)g_red)[(size_t)p * 4096 + i4] = acc;
}

// ---------------------------------------------------------------------------
// Kernel 4: reduction stage 2 — float4, mean over trees.
// ---------------------------------------------------------------------------
__global__ void reduce2_kernel(float* __restrict__ out) {
    int i4 = blockIdx.x * blockDim.x + threadIdx.x;    // 0..4095
    float4 acc = make_float4(0.f, 0.f, 0.f, 0.f);
#pragma unroll
    for (int p = 0; p < 8; p++) {
        float4 v = ((const float4*)g_red)[(size_t)p * 4096 + i4];
        acc.x += v.x; acc.y += v.y; acc.z += v.z; acc.w += v.w;
    }
    const float s = 1.f / (float)NTREES;
    ((float4*)out)[i4] = make_float4(acc.x * s, acc.y * s, acc.z * s, acc.w * s);
}

// ---------------------------------------------------------------------------
extern "C" void kernel_launch(void* const* d_in, const int* in_sizes, int n_in,
                              void* d_out, int out_size) {
    const float* x    = (const float*)d_in[0];   // (1024, 256)
    const float* fsl  = (const float*)d_in[1];   // (256, 512, 6)
    const float* th   = (const float*)d_in[2];   // (512, 6)
    const float* lt   = (const float*)d_in[3];   // (512, 6)
    const float* resp = (const float*)d_in[4];   // (512, 16, 64)
    float* out = (float*)d_out;                  // (1024, 16)

    cudaFuncSetAttribute(fv_mma_kernel,
                         cudaFuncAttributeMaxDynamicSharedMemorySize, S_TOT);

    prep_kernel<<<1024, 256>>>(fsl, x, resp);                        // 1st
    fv_mma_kernel<<<dim3(NJ / GN, BATCH / GM), 256, S_TOT>>>();      // 2nd
    resp_mma_kernel<<<dim3(NBLK, BATCH / BT), 256>>>(th, lt);        // 3rd
    reduce1_kernel<<<128, 256>>>();                                  // 4th (profiled)
    reduce2_kernel<<<16, 256>>>(out);                                // 5th
}

// round 17
// speedup vs baseline: 1.0419x; 1.0419x over previous
#include <cuda_runtime.h>
#include <cuda_fp16.h>
#include <mma.h>
#include <cstdint>

using namespace nvcuda;

// ---------------- problem dims ----------------
#define DIM     256
#define NTREES  512
#define TDEPTH  6
#define UNITS   16
#define LEAVES  64
#define BATCH   1024
#define NJ      (NTREES * TDEPTH)       // 3072 columns (j = n*6+d)

// ---------------- device scratch ----------------
__device__ __align__(16) __half g_xhi[BATCH * DIM];
__device__ __align__(16) __half g_xlo[BATCH * DIM];
__device__ __align__(16) __half g_shi[DIM * NJ];
__device__ __align__(16) __half g_slo[DIM * NJ];
__device__ __align__(16) __half g_rhi[NTREES * UNITS * LEAVES];
__device__ __align__(16) __half g_rlo[NTREES * UNITS * LEAVES];
__device__ __align__(16) float  g_fvT[(size_t)NJ * BATCH];       // 12.5 MB, [j][b]
__device__ __align__(16) float  g_partial[64 * BATCH * UNITS];   // 4 MB

__device__ __forceinline__ uint32_t h2u(__half2 h) {
    return *reinterpret_cast<uint32_t*>(&h);
}
__device__ __forceinline__ uint32_t smem_u32(const void* p) {
    uint32_t a;
    asm("{ .reg .u64 t; cvta.to.shared.u64 t, %1; cvt.u32.u64 %0, t; }" : "=r"(a) : "l"(p));
    return a;
}
__device__ __forceinline__ void cp_async16(uint32_t dst, const void* src) {
    asm volatile("cp.async.cg.shared.global [%0], [%1], 16;" :: "r"(dst), "l"(src));
}
#define CP_COMMIT()  asm volatile("cp.async.commit_group;" ::: "memory")
#define CP_WAIT(n)   asm volatile("cp.async.wait_group %0;" :: "n"(n) : "memory")

// Raw tensor-core MMA (baseline sm_80 PTX; D += A@B, fp16 in, fp32 accum).
__device__ __forceinline__ void mma16816(float d[4], const uint32_t a[4],
                                         uint32_t b0, uint32_t b1) {
    asm volatile(
        "mma.sync.aligned.m16n8k16.row.col.f32.f16.f16.f32 "
        "{%0,%1,%2,%3}, {%4,%5,%6,%7}, {%8,%9}, {%0,%1,%2,%3};"
        : "+f"(d[0]), "+f"(d[1]), "+f"(d[2]), "+f"(d[3])
        : "r"(a[0]), "r"(a[1]), "r"(a[2]), "r"(a[3]), "r"(b0), "r"(b1));
}

__device__ __forceinline__ void split4(const float* __restrict__ src,
                                       __half* dh, __half* dl, int i4) {
    float4 v = *(const float4*)(src + (size_t)i4 * 4);
    __half2 h01 = __floats2half2_rn(v.x, v.y);
    __half2 h23 = __floats2half2_rn(v.z, v.w);
    __half2 l01 = __floats2half2_rn(v.x - __low2float(h01), v.y - __high2float(h01));
    __half2 l23 = __floats2half2_rn(v.z - __low2float(h23), v.w - __high2float(h23));
    *(uint2*)(dh + (size_t)i4 * 4) = make_uint2(h2u(h01), h2u(h23));
    *(uint2*)(dl + (size_t)i4 * 4) = make_uint2(h2u(l01), h2u(l23));
}

// ---------------------------------------------------------------------------
// Kernel 0: FUSED prep — sparsemax (blocks [0,256)), x split ([256,512)),
// response split ([512,1024)).
// ---------------------------------------------------------------------------
__global__ void prep_kernel(const float* __restrict__ fsl,
                            const float* __restrict__ x,
                            const float* __restrict__ resp) {
    const int blk = blockIdx.x;
    const int tid = threadIdx.x;
    if (blk < 256) {
        int pr = blk * 256 + tid;                       // row pair 0..65535
        const float4* zp4 = (const float4*)(fsl + (size_t)pr * 12);
        float4 q0 = zp4[0], q1 = zp4[1], q2 = zp4[2];
        float vv[12] = { q0.x, q0.y, q0.z, q0.w, q1.x, q1.y,
                         q1.z, q1.w, q2.x, q2.y, q2.z, q2.w };
        __half oh[12], ol[12];
#pragma unroll
        for (int rr = 0; rr < 2; rr++) {
            float* v = vv + rr * 6;
            float s[TDEPTH];
#pragma unroll
            for (int j = 0; j < TDEPTH; j++) s[j] = v[j];
#pragma unroll
            for (int a = 0; a < TDEPTH - 1; a++)
#pragma unroll
                for (int b = 0; b < TDEPTH - 1 - a; b++)
                    if (s[b] < s[b + 1]) { float t = s[b]; s[b] = s[b + 1]; s[b + 1] = t; }
            float cs[TDEPTH], acc = 0.f; int cnt = 0;
#pragma unroll
            for (int j = 0; j < TDEPTH; j++) {
                acc += s[j]; cs[j] = acc;
                if (s[j] * (float)(j + 1) > acc - 1.f) cnt++;
            }
            float csk = cs[0];
#pragma unroll
            for (int j = 1; j < TDEPTH; j++) if (cnt == j + 1) csk = cs[j];
            float tau = (csk - 1.f) / (float)cnt;
#pragma unroll
            for (int j = 0; j < TDEPTH; j++) {
                float sv = fmaxf(v[j] - tau, 0.f);
                __half hi = __float2half_rn(sv);
                oh[rr * 6 + j] = hi;
                ol[rr * 6 + j] = __float2half_rn(sv - __half2float(hi));
            }
        }
        size_t base = (size_t)pr * 12;
        uint2* dh = (uint2*)(g_shi + base);
        uint2* dl = (uint2*)(g_slo + base);
        const uint2* sh = (const uint2*)oh;
        const uint2* sl = (const uint2*)ol;
#pragma unroll
        for (int q = 0; q < 3; q++) { dh[q] = sh[q]; dl[q] = sl[q]; }
    } else if (blk < 512) {
        split4(x, g_xhi, g_xlo, (blk - 256) * 256 + tid);
    } else {
        split4(resp, g_rhi, g_rlo, (blk - 512) * 256 + tid);
    }
}

// ---------------------------------------------------------------------------
// Kernel 1: fv GEMM via wmma, fp16 3-term split per k-chunk. GM=64 x GN=64,
// stage {x_hi,x_lo,s_hi,s_lo} double-buffered (73.7 KB) -> 3 CTAs/SM.
// ---------------------------------------------------------------------------
#define GM 64
#define GN 64
#define GK 64
#define A_LDM 72
#define B_LDM 72
#define A_BUF (GM * A_LDM)               // 4608 halves
#define B_BUF (GK * B_LDM)               // 4608 halves
#define STG_B (2 * A_BUF + 2 * B_BUF)    // 18432 halves = 36864 B
#define S_TOT (STG_B * 2 * 2)            // 73728 B

__global__ __launch_bounds__(256, 3)
void fv_mma_kernel() {
    extern __shared__ __half smh[];
    const uint32_t sbase = smem_u32(smh);

    const int tid = threadIdx.x;
    const int w   = tid >> 5;
    const int wm  = w & 1;
    const int wn  = w >> 1;
    const int j0  = blockIdx.x * GN;
    const int b0  = blockIdx.y * GM;

    auto stage = [&](int k) {
        const int k0  = k * GK;
        const uint32_t base = sbase + (uint32_t)((k & 1) * STG_B) * 2;
        const uint32_t axh = base;
        const uint32_t axl = base + (uint32_t)A_BUF * 2;
        const uint32_t bsh = base + (uint32_t)(2 * A_BUF) * 2;
        const uint32_t bsl = bsh + (uint32_t)B_BUF * 2;
#pragma unroll
        for (int q = 0; q < 2; q++) {
            int id  = tid + q * 256;
            int row = id >> 3, c16 = id & 7;
            const size_t goff = (size_t)(b0 + row) * DIM + k0 + c16 * 8;
            const uint32_t soff = (uint32_t)row * (A_LDM * 2) + c16 * 16;
            cp_async16(axh + soff, g_xhi + goff);
            cp_async16(axl + soff, g_xlo + goff);
        }
#pragma unroll
        for (int q = 0; q < 2; q++) {
            int id  = tid + q * 256;
            int row = id >> 3, c16 = id & 7;
            const size_t goff = (size_t)(k0 + row) * NJ + j0 + c16 * 8;
            const uint32_t soff = (uint32_t)row * (B_LDM * 2) + c16 * 16;
            cp_async16(bsh + soff, g_shi + goff);
            cp_async16(bsl + soff, g_slo + goff);
        }
        CP_COMMIT();
    };

    wmma::fragment<wmma::accumulator, 16, 16, 16, float> c[2];
#pragma unroll
    for (int i = 0; i < 2; i++) wmma::fill_fragment(c[i], 0.f);

    stage(0); stage(1);

#pragma unroll 1
    for (int k = 0; k < 4; k++) {
        if (k < 3) { CP_WAIT(1); } else { CP_WAIT(0); }
        __syncthreads();

        const __half* Axh = smh + (k & 1) * STG_B;
        const __half* Axl = Axh + A_BUF;
        const __half* Bsh = Axh + 2 * A_BUF;
        const __half* Bsl = Bsh + B_BUF;

#pragma unroll
        for (int kk = 0; kk < GK / 16; kk++) {
            wmma::fragment<wmma::matrix_a, 16, 16, 16, __half, wmma::row_major> ah[2], al[2];
            wmma::fragment<wmma::matrix_b, 16, 16, 16, __half, wmma::row_major> bh, bl;
#pragma unroll
            for (int i = 0; i < 2; i++) {
                wmma::load_matrix_sync(ah[i], Axh + (wm * 32 + i * 16) * A_LDM + kk * 16, A_LDM);
                wmma::load_matrix_sync(al[i], Axl + (wm * 32 + i * 16) * A_LDM + kk * 16, A_LDM);
            }
            wmma::load_matrix_sync(bh, Bsh + (kk * 16) * B_LDM + wn * 16, B_LDM);
            wmma::load_matrix_sync(bl, Bsl + (kk * 16) * B_LDM + wn * 16, B_LDM);
#pragma unroll
            for (int i = 0; i < 2; i++) {
                wmma::mma_sync(c[i], ah[i], bh, c[i]);
                wmma::mma_sync(c[i], al[i], bh, c[i]);
                wmma::mma_sync(c[i], ah[i], bl, c[i]);
            }
        }

        __syncthreads();
        if (k + 2 < 4) stage(k + 2);
    }

#pragma unroll
    for (int i = 0; i < 2; i++)
        wmma::store_matrix_sync(
            g_fvT + (size_t)(j0 + wn * 16) * BATCH + b0 + wm * 32 + i * 16,
            c[i], BATCH, wmma::mem_col_major);
}

// ---------------------------------------------------------------------------
// Kernel 2: response contraction — raw mma.sync, W built in registers.
// NT=8 trees/block -> grid 512 (single wave), 64 partial blocks.
// ---------------------------------------------------------------------------
#define BT    128
#define NT    8
#define NBLK  (NTREES / NT)             // 64
#define R_LDM 72

__global__ __launch_bounds__(256, 4)
void resp_mma_kernel(const float* __restrict__ th,
                     const float* __restrict__ lt) {
    __shared__ __half rhi_s[NT * UNITS * R_LDM];
    __shared__ __half rlo_s[NT * UNITS * R_LDM];
    __shared__ float  th_s[NT * TDEPTH], ei_s[NT * TDEPTH];

    const int tid = threadIdx.x;
    const int w   = tid >> 5;
    const int l   = tid & 31;
    const int n0  = blockIdx.x * NT;
    const int b0  = blockIdx.y * BT;

    {
        const uint2* srch = (const uint2*)(g_rhi + (size_t)(n0 * UNITS) * LEAVES);
        const uint2* srcl = (const uint2*)(g_rlo + (size_t)(n0 * UNITS) * LEAVES);
        for (int i = tid; i < NT * UNITS * LEAVES / 4; i += 256) {
            int row = i >> 4, col = (i & 15) * 4;
            *(uint2*)(rhi_s + row * R_LDM + col) = srch[i];
            *(uint2*)(rlo_s + row * R_LDM + col) = srcl[i];
        }
    }
    if (tid < NT * TDEPTH) {
        th_s[tid] = th[n0 * TDEPTH + tid];
        ei_s[tid] = __expf(-lt[n0 * TDEPTH + tid]);
    }
    __syncthreads();

    const int a  = l & 3;               // leaf-column group
    const int g  = l >> 2;              // row within half-tile / unit index
    const int bg1 = b0 + w * 16 + g;
    const int bg2 = bg1 + 8;

    float fv1[TDEPTH], fv2[TDEPTH];
#pragma unroll
    for (int d = 0; d < TDEPTH; d++) {
        fv1[d] = g_fvT[(size_t)(n0 * TDEPTH + d) * BATCH + bg1];
        fv2[d] = g_fvT[(size_t)(n0 * TDEPTH + d) * BATCH + bg2];
    }

    float D0[4] = {0.f, 0.f, 0.f, 0.f};
    float D1[4] = {0.f, 0.f, 0.f, 0.f};

#pragma unroll 1
    for (int t = 0; t < NT; t++) {
        float wA[2], wB[2];
        float t4[2][2][2];
        float g5p[2], g5n[2];
#pragma unroll
        for (int r = 0; r < 2; r++) {
            const float* fv = r ? fv2 : fv1;
            float gp[TDEPTH], gn[TDEPTH];
#pragma unroll
            for (int d = 0; d < TDEPTH; d++) {
                float tt = (fv[d] - th_s[t * TDEPTH + d]) * ei_s[t * TDEPTH + d];
                gp[d] = __saturatef(fmaf(0.5f, tt, 0.5f));
                gn[d] = 1.f - gp[d];
            }
            float g1s = (a & 1) ? gn[1] : gp[1];
            wA[r] = gp[0] * g1s;
            wB[r] = gn[0] * g1s;
            float g2s = (a >> 1) ? gn[2] : gp[2];
            float t3p = g2s * gp[3], t3n = g2s * gn[3];
            t4[r][0][0] = t3p * gp[4]; t4[r][0][1] = t3n * gp[4];
            t4[r][1][0] = t3p * gn[4]; t4[r][1][1] = t3n * gn[4];
            g5p[r] = gp[5]; g5n[r] = gn[5];
        }

        if (t < NT - 1) {
#pragma unroll
            for (int d = 0; d < TDEPTH; d++) {
                fv1[d] = g_fvT[(size_t)((n0 + t + 1) * TDEPTH + d) * BATCH + bg1];
                fv2[d] = g_fvT[(size_t)((n0 + t + 1) * TDEPTH + d) * BATCH + bg2];
            }
        }

        const __half* rh = rhi_s + t * UNITS * R_LDM;
        const __half* rl = rlo_s + t * UNITS * R_LDM;

#pragma unroll
        for (int kk = 0; kk < 4; kk++) {
            uint32_t Ahi[4], Alo[4];
#pragma unroll
            for (int r = 0; r < 2; r++) {
                float g5s  = (kk >> 1) ? g5n[r] : g5p[r];
                float whiL = t4[r][kk & 1][0] * g5s;
                float whiH = t4[r][kk & 1][1] * g5s;
                float w0 = wA[r] * whiL, w1 = wB[r] * whiL;
                float w2 = wA[r] * whiH, w3 = wB[r] * whiH;
                __half2 hL = __floats2half2_rn(w0, w1);
                __half2 hH = __floats2half2_rn(w2, w3);
                float2 fL = __half22float2(hL);
                float2 fH = __half22float2(hH);
                __half2 lL = __floats2half2_rn(w0 - fL.x, w1 - fL.y);
                __half2 lH = __floats2half2_rn(w2 - fH.x, w3 - fH.y);
                Ahi[r]     = h2u(hL);  Ahi[2 + r] = h2u(hH);
                Alo[r]     = h2u(lL);  Alo[2 + r] = h2u(lH);
            }
            const int off = kk * 16 + a * 2;
            uint32_t bh0 = *(const uint32_t*)(rh + g * R_LDM + off);
            uint32_t bh1 = *(const uint32_t*)(rh + g * R_LDM + off + 8);
            uint32_t bh2 = *(const uint32_t*)(rh + (8 + g) * R_LDM + off);
            uint32_t bh3 = *(const uint32_t*)(rh + (8 + g) * R_LDM + off + 8);
            uint32_t bl0 = *(const uint32_t*)(rl + g * R_LDM + off);
            uint32_t bl1 = *(const uint32_t*)(rl + g * R_LDM + off + 8);
            uint32_t bl2 = *(const uint32_t*)(rl + (8 + g) * R_LDM + off);
            uint32_t bl3 = *(const uint32_t*)(rl + (8 + g) * R_LDM + off + 8);

            mma16816(D0, Ahi, bh0, bh1);
            mma16816(D1, Ahi, bh2, bh3);
            mma16816(D0, Alo, bh0, bh1);
            mma16816(D1, Alo, bh2, bh3);
            mma16816(D0, Ahi, bl0, bl1);
            mma16816(D1, Ahi, bl2, bl3);
        }
    }

    float* p1 = g_partial + ((size_t)blockIdx.x * BATCH + bg1) * UNITS;
    float* p2 = g_partial + ((size_t)blockIdx.x * BATCH + bg2) * UNITS;
    *(float2*)(p1 + a * 2)     = make_float2(D0[0], D0[1]);
    *(float2*)(p2 + a * 2)     = make_float2(D0[2], D0[3]);
    *(float2*)(p1 + 8 + a * 2) = make_float2(D1[0], D1[1]);
    *(float2*)(p2 + 8 + a * 2) = make_float2(D1[2], D1[3]);
}

// ---------------------------------------------------------------------------
// Kernel 3: one-shot reduction — one warp per float4 output column.
// Lane k sums partial rows k and k+32 (2 independent LD.128), then a 5-round
// shfl_xor butterfly (deterministic fixed order); lane 0 stores the mean.
// 4096 warps = 512 CTAs.
// ---------------------------------------------------------------------------
__global__ void reduce_kernel(float* __restrict__ out) {
    const int wid  = (blockIdx.x * blockDim.x + threadIdx.x) >> 5;   // 0..4095
    const int lane = threadIdx.x & 31;
    const float4* P = (const float4*)g_partial;
    float4 a = P[(size_t)lane * 4096 + wid];
    float4 b = P[(size_t)(lane + 32) * 4096 + wid];
    float4 v = make_float4(a.x + b.x, a.y + b.y, a.z + b.z, a.w + b.w);
#pragma unroll
    for (int off = 16; off >= 1; off >>= 1) {
        v.x += __shfl_xor_sync(0xFFFFFFFFu, v.x, off);
        v.y += __shfl_xor_sync(0xFFFFFFFFu, v.y, off);
        v.z += __shfl_xor_sync(0xFFFFFFFFu, v.z, off);
        v.w += __shfl_xor_sync(0xFFFFFFFFu, v.w, off);
    }
    if (lane == 0) {
        const float s = 1.f / (float)NTREES;
        ((float4*)out)[wid] = make_float4(v.x * s, v.y * s, v.z * s, v.w * s);
    }
}

// ---------------------------------------------------------------------------
extern "C" void kernel_launch(void* const* d_in, const int* in_sizes, int n_in,
                              void* d_out, int out_size) {
    const float* x    = (const float*)d_in[0];   // (1024, 256)
    const float* fsl  = (const float*)d_in[1];   // (256, 512, 6)
    const float* th   = (const float*)d_in[2];   // (512, 6)
    const float* lt   = (const float*)d_in[3];   // (512, 6)
    const float* resp = (const float*)d_in[4];   // (512, 16, 64)
    float* out = (float*)d_out;                  // (1024, 16)

    cudaFuncSetAttribute(fv_mma_kernel,
                         cudaFuncAttributeMaxDynamicSharedMemorySize, S_TOT);

    prep_kernel<<<1024, 256>>>(fsl, x, resp);                        // 1st
    fv_mma_kernel<<<dim3(NJ / GN, BATCH / GM), 256, S_TOT>>>();      // 2nd
    resp_mma_kernel<<<dim3(NBLK, BATCH / BT), 256>>>(th, lt);        // 3rd
    reduce_kernel<<<512, 256>>>(out);                                // 4th (profiled)
}